// round 3
// baseline (speedup 1.0000x reference)
#include <cuda_runtime.h>

#define VOCAB  50000
#define EMBED  256
#define MAXLEN 512
#define UNITS  32
#define F1     16
#define BATCH  512

// Scratch: projected embedding table P[v][u] = sum_e emb[v][e]*Wx[e][u], prescaled
// by 2*log2(e) so the recurrence can feed ex2 directly.
__device__ float g_P[VOCAB * UNITS];

#define TANH_SCALE 2.8853900817779268f   // 2*log2(e)

// ---------------------------------------------------------------------------
// Kernel A: P = (emb_table @ Wx) * TANH_SCALE   (unchanged from R1, ~17us,
// near its FMA-issue floor of ~11us; not the bottleneck)
// ---------------------------------------------------------------------------
__global__ void __launch_bounds__(128) proj_kernel(
    const float* __restrict__ emb, const float* __restrict__ Wx)
{
    __shared__ float sW[EMBED * UNITS];
    const int t = threadIdx.x;
    for (int i = t; i < EMBED * UNITS / 4; i += 128)
        ((float4*)sW)[i] = ((const float4*)Wx)[i];
    __syncthreads();

    const int ug    = t & 3;
    const int s     = t >> 2;
    const int rbase = blockIdx.x * 128 + s * 4;

    float acc[4][8];
    #pragma unroll
    for (int rr = 0; rr < 4; rr++)
        #pragma unroll
        for (int j = 0; j < 8; j++) acc[rr][j] = 0.f;

    const float* arow[4];
    #pragma unroll
    for (int rr = 0; rr < 4; rr++) {
        int r = rbase + rr;
        if (r >= VOCAB) r = VOCAB - 1;
        arow[rr] = emb + (size_t)r * EMBED;
    }

    for (int e0 = 0; e0 < EMBED; e0 += 4) {
        float4 av[4];
        #pragma unroll
        for (int rr = 0; rr < 4; rr++)
            av[rr] = *(const float4*)(arow[rr] + e0);

        #pragma unroll
        for (int ee = 0; ee < 4; ee++) {
            const float4 w0 = *(const float4*)&sW[(e0 + ee) * UNITS + ug * 8];
            const float4 w1 = *(const float4*)&sW[(e0 + ee) * UNITS + ug * 8 + 4];
            #pragma unroll
            for (int rr = 0; rr < 4; rr++) {
                const float a = ((const float*)&av[rr])[ee];
                acc[rr][0] = fmaf(a, w0.x, acc[rr][0]);
                acc[rr][1] = fmaf(a, w0.y, acc[rr][1]);
                acc[rr][2] = fmaf(a, w0.z, acc[rr][2]);
                acc[rr][3] = fmaf(a, w0.w, acc[rr][3]);
                acc[rr][4] = fmaf(a, w1.x, acc[rr][4]);
                acc[rr][5] = fmaf(a, w1.y, acc[rr][5]);
                acc[rr][6] = fmaf(a, w1.z, acc[rr][6]);
                acc[rr][7] = fmaf(a, w1.w, acc[rr][7]);
            }
        }
    }

    #pragma unroll
    for (int rr = 0; rr < 4; rr++) {
        const int r = rbase + rr;
        if (r < VOCAB) {
            float4 o0, o1;
            o0.x = acc[rr][0] * TANH_SCALE; o0.y = acc[rr][1] * TANH_SCALE;
            o0.z = acc[rr][2] * TANH_SCALE; o0.w = acc[rr][3] * TANH_SCALE;
            o1.x = acc[rr][4] * TANH_SCALE; o1.y = acc[rr][5] * TANH_SCALE;
            o1.z = acc[rr][6] * TANH_SCALE; o1.w = acc[rr][7] * TANH_SCALE;
            *(float4*)&g_P[r * UNITS + ug * 8]     = o0;
            *(float4*)&g_P[r * UNITS + ug * 8 + 4] = o1;
        }
    }
}

// ---------------------------------------------------------------------------
// Kernel B: recurrence + head. One warp per batch row, lane u owns unit u.
// Recurrent state is r = 1/(1 + e^(2x)) (so h = 1 - 2r), which retires from
// RCP and is shuffled IMMEDIATELY; the affine (1-2r) is folded into the
// weights:  sum_v h[v]Wh[v][u] = colsum[u] - 2*sum_v r[v]Wh[v][u].
// All 32 shfls go to independent temps (pure ILP), then 32 FMA into 8
// accumulators (chain depth 4) + 3-level tree.
// ---------------------------------------------------------------------------
__global__ void __launch_bounds__(128) rnn_kernel(
    const int*   __restrict__ tokens,
    const float* __restrict__ Wh,
    const float* __restrict__ bvec,
    const float* __restrict__ W1,
    const float* __restrict__ b1,
    const float* __restrict__ W2,
    const float* __restrict__ b2,
    float*       __restrict__ out)
{
    __shared__ int sTok[4 * MAXLEN];
    const int tid  = threadIdx.x;
    const int wid  = tid >> 5;
    const int lane = tid & 31;
    const int b0   = blockIdx.x * 4;

    for (int i = tid; i < 4 * MAXLEN; i += 128)
        sTok[i] = tokens[b0 * MAXLEN + i];
    __syncthreads();

    const int* myTok = sTok + wid * MAXLEN;
    const int  brow  = b0 + wid;

    // wh2[v] = -2*SCALE*Wh[v][lane];  cbias = SCALE*(b[lane] + colsum[lane])
    float wh2[32];
    float cs = 0.f;
    #pragma unroll
    for (int v = 0; v < 32; v++) {
        const float w = Wh[v * UNITS + lane];
        cs += w;
        wh2[v] = w * (-2.0f * TANH_SCALE);
    }
    const float cbias = (bvec[lane] + cs) * TANH_SCALE;

    float xwv[4];
    #pragma unroll
    for (int j = 0; j < 4; j++)
        xwv[j] = g_P[myTok[j] * UNITS + lane];

    float r = 0.5f;                         // h = 1 - 2r = 0
    for (int t0 = 0; t0 < MAXLEN; t0 += 4) {
        #pragma unroll
        for (int j = 0; j < 4; j++) {
            const float xw = xwv[j];
            int tn = t0 + j + 4;
            tn = (tn < MAXLEN) ? tn : (MAXLEN - 1);   // branch-free clamp
            xwv[j] = g_P[myTok[tn] * UNITS + lane];

            // All 32 shfls first: independent temps, maximal ILP.
            float rs[32];
            #pragma unroll
            for (int v = 0; v < 32; v++)
                rs[v] = __shfl_sync(0xffffffffu, r, v);

            float a0 = xw + cbias;
            float a1 = 0.f, a2 = 0.f, a3 = 0.f;
            float a4 = 0.f, a5 = 0.f, a6 = 0.f, a7 = 0.f;
            #pragma unroll
            for (int v = 0; v < 32; v += 8) {
                a0 = fmaf(rs[v + 0], wh2[v + 0], a0);
                a1 = fmaf(rs[v + 1], wh2[v + 1], a1);
                a2 = fmaf(rs[v + 2], wh2[v + 2], a2);
                a3 = fmaf(rs[v + 3], wh2[v + 3], a3);
                a4 = fmaf(rs[v + 4], wh2[v + 4], a4);
                a5 = fmaf(rs[v + 5], wh2[v + 5], a5);
                a6 = fmaf(rs[v + 6], wh2[v + 6], a6);
                a7 = fmaf(rs[v + 7], wh2[v + 7], a7);
            }
            const float z2 = ((a0 + a1) + (a2 + a3)) + ((a4 + a5) + (a6 + a7));
            // r = 1 / (1 + e^(2x)),  z2 = 2*log2(e)*x
            float e, rn;
            asm("ex2.approx.f32 %0, %1;" : "=f"(e) : "f"(z2));
            asm("rcp.approx.f32 %0, %1;" : "=f"(rn) : "f"(e + 1.0f));
            r = rn;
        }
    }

    const float h = fmaf(-2.0f, r, 1.0f);   // final hidden value for lane

    // Head: f = h@W1 + b1 (16), z = f@W2 + b2, out = sigmoid(z)
    float facc = 0.f;
    #pragma unroll
    for (int v = 0; v < 32; v++) {
        const float hv = __shfl_sync(0xffffffffu, h, v);
        if (lane < F1)
            facc = fmaf(hv, W1[v * F1 + lane], facc);
    }
    float p = 0.f;
    if (lane < F1) p = (facc + b1[lane]) * W2[lane];
    #pragma unroll
    for (int off = 16; off > 0; off >>= 1)
        p += __shfl_xor_sync(0xffffffffu, p, off);

    if (lane == 0) {
        const float z = p + b2[0];
        float e, rr;
        asm("ex2.approx.f32 %0, %1;" : "=f"(e) : "f"(-z * 1.4426950408889634f));
        asm("rcp.approx.f32 %0, %1;" : "=f"(rr) : "f"(1.0f + e));
        out[brow] = rr;
    }
}

// ---------------------------------------------------------------------------
extern "C" void kernel_launch(void* const* d_in, const int* in_sizes, int n_in,
                              void* d_out, int out_size)
{
    const int*   tokens = (const int*)  d_in[0];
    const float* emb    = (const float*)d_in[1];
    const float* Wx     = (const float*)d_in[2];
    const float* Wh     = (const float*)d_in[3];
    const float* b      = (const float*)d_in[4];
    const float* W1     = (const float*)d_in[5];
    const float* b1     = (const float*)d_in[6];
    const float* W2     = (const float*)d_in[7];
    const float* b2     = (const float*)d_in[8];
    float* out = (float*)d_out;

    proj_kernel<<<(VOCAB + 127) / 128, 128>>>(emb, Wx);
    rnn_kernel<<<BATCH / 4, 128>>>(tokens, Wh, b, W1, b1, W2, b2, out);
}

// round 6
// speedup vs baseline: 1.5840x; 1.5840x over previous
#include <cuda_runtime.h>
#include <cstdint>

#define VOCAB  50000
#define EMBED  256
#define MAXLEN 512
#define UNITS  32
#define F1     16
#define BATCH  512

// Scratch: projected embedding table P[v][u] = sum_e emb[v][e]*Wx[e][u], prescaled
// by 2*log2(e) so the recurrence can feed ex2 directly.
__device__ float g_P[VOCAB * UNITS];

#define TANH_SCALE 2.8853900817779268f   // 2*log2(e)

// ---------------------------------------------------------------------------
// Packed f32x2 helpers
// ---------------------------------------------------------------------------
__device__ __forceinline__ unsigned long long pk2(float lo, float hi) {
    unsigned long long r;
    asm("mov.b64 %0, {%1, %2};" : "=l"(r) : "f"(lo), "f"(hi));
    return r;
}
__device__ __forceinline__ void upk2(float& lo, float& hi, unsigned long long v) {
    asm("mov.b64 {%0, %1}, %2;" : "=f"(lo), "=f"(hi) : "l"(v));
}
__device__ __forceinline__ unsigned long long fma2(
    unsigned long long a, unsigned long long b, unsigned long long c) {
    unsigned long long d;
    asm("fma.rn.f32x2 %0, %1, %2, %3;" : "=l"(d) : "l"(a), "l"(b), "l"(c));
    return d;
}
__device__ __forceinline__ unsigned long long add2(
    unsigned long long a, unsigned long long b) {
    unsigned long long d;
    asm("add.rn.f32x2 %0, %1, %2;" : "=l"(d) : "l"(a), "l"(b));
    return d;
}

// ---------------------------------------------------------------------------
// Kernel A: P = (emb_table @ Wx) * TANH_SCALE   (~17us, near FMA-issue floor;
// not the bottleneck — unchanged)
// ---------------------------------------------------------------------------
__global__ void __launch_bounds__(128) proj_kernel(
    const float* __restrict__ emb, const float* __restrict__ Wx)
{
    __shared__ float sW[EMBED * UNITS];
    const int t = threadIdx.x;
    for (int i = t; i < EMBED * UNITS / 4; i += 128)
        ((float4*)sW)[i] = ((const float4*)Wx)[i];
    __syncthreads();

    const int ug    = t & 3;
    const int s     = t >> 2;
    const int rbase = blockIdx.x * 128 + s * 4;

    float acc[4][8];
    #pragma unroll
    for (int rr = 0; rr < 4; rr++)
        #pragma unroll
        for (int j = 0; j < 8; j++) acc[rr][j] = 0.f;

    const float* arow[4];
    #pragma unroll
    for (int rr = 0; rr < 4; rr++) {
        int r = rbase + rr;
        if (r >= VOCAB) r = VOCAB - 1;
        arow[rr] = emb + (size_t)r * EMBED;
    }

    for (int e0 = 0; e0 < EMBED; e0 += 4) {
        float4 av[4];
        #pragma unroll
        for (int rr = 0; rr < 4; rr++)
            av[rr] = *(const float4*)(arow[rr] + e0);

        #pragma unroll
        for (int ee = 0; ee < 4; ee++) {
            const float4 w0 = *(const float4*)&sW[(e0 + ee) * UNITS + ug * 8];
            const float4 w1 = *(const float4*)&sW[(e0 + ee) * UNITS + ug * 8 + 4];
            #pragma unroll
            for (int rr = 0; rr < 4; rr++) {
                const float a = ((const float*)&av[rr])[ee];
                acc[rr][0] = fmaf(a, w0.x, acc[rr][0]);
                acc[rr][1] = fmaf(a, w0.y, acc[rr][1]);
                acc[rr][2] = fmaf(a, w0.z, acc[rr][2]);
                acc[rr][3] = fmaf(a, w0.w, acc[rr][3]);
                acc[rr][4] = fmaf(a, w1.x, acc[rr][4]);
                acc[rr][5] = fmaf(a, w1.y, acc[rr][5]);
                acc[rr][6] = fmaf(a, w1.z, acc[rr][6]);
                acc[rr][7] = fmaf(a, w1.w, acc[rr][7]);
            }
        }
    }

    #pragma unroll
    for (int rr = 0; rr < 4; rr++) {
        const int r = rbase + rr;
        if (r < VOCAB) {
            float4 o0, o1;
            o0.x = acc[rr][0] * TANH_SCALE; o0.y = acc[rr][1] * TANH_SCALE;
            o0.z = acc[rr][2] * TANH_SCALE; o0.w = acc[rr][3] * TANH_SCALE;
            o1.x = acc[rr][4] * TANH_SCALE; o1.y = acc[rr][5] * TANH_SCALE;
            o1.z = acc[rr][6] * TANH_SCALE; o1.w = acc[rr][7] * TANH_SCALE;
            *(float4*)&g_P[r * UNITS + ug * 8]     = o0;
            *(float4*)&g_P[r * UNITS + ug * 8 + 4] = o1;
        }
    }
}

// ---------------------------------------------------------------------------
// Kernel B: recurrence + head. One warp per batch row, lane u owns unit u.
// State r = 1/(1+e^(2x)) (h = 1-2r); affine folded into weights:
//   sum_v h[v]Wh[v][u] = colsum[u] - 2*sum_v r[v]Wh[v][u].
// Broadcast of the 32-lane r vector goes through SMEM (1 STS + syncwarp +
// 8 LDS.128 broadcast) instead of 32 MIO-throttled SHFLs, and the matvec
// uses 16 packed fma.rn.f32x2 into 8 packed accumulators + packed add tree.
// ---------------------------------------------------------------------------
__global__ void __launch_bounds__(128, 1) rnn_kernel(
    const int*   __restrict__ tokens,
    const float* __restrict__ Wh,
    const float* __restrict__ bvec,
    const float* __restrict__ W1,
    const float* __restrict__ b1,
    const float* __restrict__ W2,
    const float* __restrict__ b2,
    float*       __restrict__ out)
{
    __shared__ int   sTok[4 * MAXLEN];
    __shared__ float sR[4][32];             // 128B row per warp, 16B aligned

    const int tid  = threadIdx.x;
    const int wid  = tid >> 5;
    const int lane = tid & 31;
    const int b0   = blockIdx.x * 4;

    for (int i = tid; i < 4 * MAXLEN; i += 128)
        sTok[i] = tokens[b0 * MAXLEN + i];
    __syncthreads();

    const int* myTok = sTok + wid * MAXLEN;
    const int  brow  = b0 + wid;

    // Packed column weights: wpk[k] = {-2S*Wh[2k][lane], -2S*Wh[2k+1][lane]}
    unsigned long long wpk[16];
    float cs = 0.f;
    #pragma unroll
    for (int v = 0; v < 32; v += 2) {
        const float w0 = Wh[v * UNITS + lane];
        const float w1 = Wh[(v + 1) * UNITS + lane];
        cs += w0 + w1;
        wpk[v >> 1] = pk2(w0 * (-2.0f * TANH_SCALE), w1 * (-2.0f * TANH_SCALE));
    }
    const float cbias = (bvec[lane] + cs) * TANH_SCALE;

    float xwv[4];
    #pragma unroll
    for (int j = 0; j < 4; j++)
        xwv[j] = g_P[myTok[j] * UNITS + lane];

    const ulonglong2* rrow = (const ulonglong2*)sR[wid];   // 8 x 16B

    float r = 0.5f;                         // h = 1 - 2r = 0
    for (int t0 = 0; t0 < MAXLEN; t0 += 4) {
        #pragma unroll
        for (int j = 0; j < 4; j++) {
            const float xw = xwv[j];
            int tn = t0 + j + 4;
            tn = (tn < MAXLEN) ? tn : (MAXLEN - 1);   // branch-free clamp
            xwv[j] = g_P[myTok[tn] * UNITS + lane];

            sR[wid][lane] = r;
            __syncwarp();

            unsigned long long acc[8];
            acc[0] = pk2(xw + cbias, 0.f);
            #pragma unroll
            for (int i = 1; i < 8; i++) acc[i] = pk2(0.f, 0.f);

            #pragma unroll
            for (int i = 0; i < 8; i++) {
                const ulonglong2 q = rrow[i];          // LDS.128 broadcast
                acc[i] = fma2(q.x, wpk[2 * i],     acc[i]);
                acc[i] = fma2(q.y, wpk[2 * i + 1], acc[i]);
            }

            const unsigned long long s0 = add2(acc[0], acc[1]);
            const unsigned long long s1 = add2(acc[2], acc[3]);
            const unsigned long long s2 = add2(acc[4], acc[5]);
            const unsigned long long s3 = add2(acc[6], acc[7]);
            const unsigned long long t1 = add2(s0, s1);
            const unsigned long long t2 = add2(s2, s3);
            const unsigned long long u  = add2(t1, t2);
            float lo, hi;
            upk2(lo, hi, u);
            const float z2 = lo + hi;      // = 2*log2(e) * preact
            float e, rn;
            asm("ex2.approx.f32 %0, %1;" : "=f"(e) : "f"(z2));
            asm("rcp.approx.f32 %0, %1;" : "=f"(rn) : "f"(e + 1.0f));
            r = rn;
        }
    }

    const float h = fmaf(-2.0f, r, 1.0f);   // final hidden value for lane

    // Head: f = h@W1 + b1 (16), z = f@W2 + b2, out = sigmoid(z)  (one-time)
    float facc = 0.f;
    #pragma unroll
    for (int v = 0; v < 32; v++) {
        const float hv = __shfl_sync(0xffffffffu, h, v);
        if (lane < F1)
            facc = fmaf(hv, W1[v * F1 + lane], facc);
    }
    float p = 0.f;
    if (lane < F1) p = (facc + b1[lane]) * W2[lane];
    #pragma unroll
    for (int off = 16; off > 0; off >>= 1)
        p += __shfl_xor_sync(0xffffffffu, p, off);

    if (lane == 0) {
        const float z = p + b2[0];
        float e, rr;
        asm("ex2.approx.f32 %0, %1;" : "=f"(e) : "f"(-z * 1.4426950408889634f));
        asm("rcp.approx.f32 %0, %1;" : "=f"(rr) : "f"(1.0f + e));
        out[brow] = rr;
    }
}

// ---------------------------------------------------------------------------
extern "C" void kernel_launch(void* const* d_in, const int* in_sizes, int n_in,
                              void* d_out, int out_size)
{
    const int*   tokens = (const int*)  d_in[0];
    const float* emb    = (const float*)d_in[1];
    const float* Wx     = (const float*)d_in[2];
    const float* Wh     = (const float*)d_in[3];
    const float* b      = (const float*)d_in[4];
    const float* W1     = (const float*)d_in[5];
    const float* b1     = (const float*)d_in[6];
    const float* W2     = (const float*)d_in[7];
    const float* b2     = (const float*)d_in[8];
    float* out = (float*)d_out;

    proj_kernel<<<(VOCAB + 127) / 128, 128>>>(emb, Wx);
    rnn_kernel<<<BATCH / 4, 128>>>(tokens, Wh, b, W1, b1, W2, b2, out);
}